// round 16
// baseline (speedup 1.0000x reference)
#include <cuda_runtime.h>
#include <cuda_bf16.h>
#include <cstdint>

// Problem constants
#define BB    8
#define NN    4096
#define DIMV  768
#define HEADS 12
#define HD    64
#define EDIM  1536
#define MTOT  (BB*NN)   // 32768
#define KTV_SPLIT 32
#define NQKV  2304      // merged q|kv output width

// Scratch (static device allocations)
__device__ float g_q   [(size_t)MTOT * DIMV];
__device__ float g_kv  [(size_t)MTOT * EDIM];   // k cols 0..767 softmaxed (fused)
__device__ float g_ktvp[(size_t)KTV_SPLIT * BB * HEADS * HD * HD];
__device__ float g_ektv[BB * 2*HEADS * HD * HD];

// bf16 hi/lo split operands
__device__ __nv_bfloat16 g_xh[(size_t)MTOT * DIMV];
__device__ __nv_bfloat16 g_xl[(size_t)MTOT * DIMV];
__device__ __nv_bfloat16 g_yh[(size_t)MTOT * EDIM];
__device__ __nv_bfloat16 g_yl[(size_t)MTOT * EDIM];
// weights transposed to [N][K] + split; q|kv merged
__device__ __nv_bfloat16 g_wqkvh[NQKV * DIMV];
__device__ __nv_bfloat16 g_wqkvl[NQKV * DIMV];
__device__ __nv_bfloat16 g_wph  [DIMV * EDIM];
__device__ __nv_bfloat16 g_wpl  [DIMV * EDIM];

// ---------------------------------------------------------------------------
// MMA / cp.async helpers
// ---------------------------------------------------------------------------
__device__ __forceinline__ void ldsm_x4p(uint32_t r[4], const void* p) {
    uint32_t a = (uint32_t)__cvta_generic_to_shared(p);
    asm volatile("ldmatrix.sync.aligned.m8n8.x4.shared.b16 {%0,%1,%2,%3}, [%4];"
                 : "=r"(r[0]), "=r"(r[1]), "=r"(r[2]), "=r"(r[3]) : "r"(a));
}
__device__ __forceinline__ void mma16816(float c[4], const uint32_t a[4],
                                         uint32_t b0, uint32_t b1) {
    asm volatile(
        "mma.sync.aligned.m16n8k16.row.col.f32.bf16.bf16.f32 "
        "{%0,%1,%2,%3}, {%4,%5,%6,%7}, {%8,%9}, {%0,%1,%2,%3};"
        : "+f"(c[0]), "+f"(c[1]), "+f"(c[2]), "+f"(c[3])
        : "r"(a[0]), "r"(a[1]), "r"(a[2]), "r"(a[3]), "r"(b0), "r"(b1));
}
__device__ __forceinline__ void cp_async16(void* smem_dst, const void* gsrc) {
    uint32_t a = (uint32_t)__cvta_generic_to_shared(smem_dst);
    asm volatile("cp.async.cg.shared.global [%0], [%1], 16;" :: "r"(a), "l"(gsrc));
}
#define CP_COMMIT() asm volatile("cp.async.commit_group;" ::: "memory")
#define CP_WAIT0()  asm volatile("cp.async.wait_group 0;" ::: "memory")
#define CP_WAIT1()  asm volatile("cp.async.wait_group 1;" ::: "memory")

// SW128 swizzle on (row, 16B-chunk) within a 128x32 bf16 tile (64 B rows)
__device__ __forceinline__ int sw_off(int row, int chunk) {
    int byte = row * 64 + chunk * 16;
    return byte ^ ((byte >> 3) & 0x70);
}

#define TILE_SW  8192                 // one 128x32 bf16 tile, swizzled, no pad
#define STAGE_SW (4 * TILE_SW)        // Ah, Al, Bh, Bl  = 32768 B
#define NSTAGE   3
#define GEMM_DSMEM (NSTAGE * STAGE_SW)  // 98304 B

// ---------------------------------------------------------------------------
// bf16x3 tensor-core GEMM, pre-split operands, 3-stage cp.async pipeline.
// Inner loop software-pipelines B fragments (double-buffered at n2 level)
// so ldsm latency overlaps MMA issue. 128x128 tile, BK=32, 2 CTAs/SM.
// C routed by column: col < csplit -> C1 (ld1), else C2 (ld2, col-csplit).
// Softmax over 64-col heads applied for cols in [sm_lo, sm_hi).
// ---------------------------------------------------------------------------
__global__ __launch_bounds__(256, 2) void gemm_mma(
    const __nv_bfloat16* __restrict__ Ah, const __nv_bfloat16* __restrict__ Al,
    const __nv_bfloat16* __restrict__ Bh, const __nv_bfloat16* __restrict__ Bl,
    float* __restrict__ C1, float* __restrict__ C2, int csplit, int ld1, int ld2,
    int M, int N, int K, const float* __restrict__ bias, int sm_lo, int sm_hi)
{
    extern __shared__ char smem[];

    const int tid  = threadIdx.x;
    const int lane = tid & 31;
    const int warp = tid >> 5;
    const int warpM = warp >> 1;
    const int warpN = warp & 1;
    const int bm = blockIdx.y * 128;
    const int bn = blockIdx.x * 128;

    float acc[2][8][4];
#pragma unroll
    for (int i = 0; i < 2; i++)
#pragma unroll
        for (int j = 0; j < 8; j++)
#pragma unroll
            for (int l = 0; l < 4; l++) acc[i][j][l] = 0.f;

    const int aRow = warpM * 32 + (lane & 7) + ((lane & 8) ? 8 : 0);
    const int bRow = warpN * 64 + (lane & 7) + ((lane & 16) ? 8 : 0);

    // precomputed swizzled ldsm offsets (loop-invariant; only stage base moves)
    int offA[2][2], offB[4][2];
#pragma unroll
    for (int mi = 0; mi < 2; mi++)
#pragma unroll
        for (int ks = 0; ks < 2; ks++)
            offA[mi][ks] = sw_off(aRow + mi * 16, ks * 2 + ((lane & 16) ? 1 : 0));
#pragma unroll
    for (int n2 = 0; n2 < 4; n2++)
#pragma unroll
        for (int ks = 0; ks < 2; ks++)
            offB[n2][ks] = sw_off(bRow + n2 * 16, ks * 2 + ((lane & 8) ? 1 : 0));

    // staging: row = tid>>1, two 16B chunks per piece
    const __nv_bfloat16* srcs[4] = {Ah, Al, Bh, Bl};
    const int rowbase[4] = {bm, bm, bn, bn};
    const int row = tid >> 1;
    const int ch0 = (tid & 1) * 2;
    int stg_off[2];
    stg_off[0] = sw_off(row, ch0);
    stg_off[1] = sw_off(row, ch0 + 1);

    auto issue_stage = [&](int kt, int sidx) {
        char* st = smem + sidx * STAGE_SW;
        const int k0 = kt << 5;
#pragma unroll
        for (int p = 0; p < 4; p++) {
            const __nv_bfloat16* src = srcs[p] + (size_t)(rowbase[p] + row) * K + k0;
#pragma unroll
            for (int c = 0; c < 2; c++)
                cp_async16(st + p * TILE_SW + stg_off[c], src + (ch0 + c) * 8);
        }
    };

    const int NK = K >> 5;
    issue_stage(0, 0);
    CP_COMMIT();
    issue_stage(1, 1);
    CP_COMMIT();

    int s3 = 0;                         // kt % 3
    for (int kt = 0; kt < NK; kt++) {
        if (kt == NK - 1) { CP_WAIT0(); } else { CP_WAIT1(); }
        __syncthreads();
        if (kt + 2 < NK) {
            int si = s3 + 2; if (si >= 3) si -= 3;
            issue_stage(kt + 2, si);
            CP_COMMIT();
        }

        const char* st = smem + s3 * STAGE_SW;
#pragma unroll
        for (int ks = 0; ks < 2; ks++) {
            uint32_t ah[2][4], al[2][4];
#pragma unroll
            for (int mi = 0; mi < 2; mi++) {
                ldsm_x4p(ah[mi], st + offA[mi][ks]);
                ldsm_x4p(al[mi], st + TILE_SW + offA[mi][ks]);
            }
            // B double buffer: prefetch group n2+1 while computing group n2
            uint32_t bh[2][4], bl[2][4];
            ldsm_x4p(bh[0], st + 2 * TILE_SW + offB[0][ks]);
            ldsm_x4p(bl[0], st + 3 * TILE_SW + offB[0][ks]);
#pragma unroll
            for (int n2 = 0; n2 < 4; n2++) {
                const int cur = n2 & 1, nxt = cur ^ 1;
                if (n2 < 3) {
                    ldsm_x4p(bh[nxt], st + 2 * TILE_SW + offB[n2 + 1][ks]);
                    ldsm_x4p(bl[nxt], st + 3 * TILE_SW + offB[n2 + 1][ks]);
                }
#pragma unroll
                for (int mi = 0; mi < 2; mi++) {
                    mma16816(acc[mi][2*n2],   ah[mi], bh[cur][0], bh[cur][1]);
                    mma16816(acc[mi][2*n2+1], ah[mi], bh[cur][2], bh[cur][3]);
                    mma16816(acc[mi][2*n2],   ah[mi], bl[cur][0], bl[cur][1]);
                    mma16816(acc[mi][2*n2+1], ah[mi], bl[cur][2], bl[cur][3]);
                    mma16816(acc[mi][2*n2],   al[mi], bh[cur][0], bh[cur][1]);
                    mma16816(acc[mi][2*n2+1], al[mi], bh[cur][2], bh[cur][3]);
                }
            }
        }
        if (++s3 == 3) s3 = 0;
    }

    const int colbase = bn + warpN * 64;

    // fused softmax over 64-col heads (k region of merged qkv projection)
    if (colbase >= sm_lo && colbase < sm_hi) {
#pragma unroll
        for (int mi = 0; mi < 2; mi++) {
#pragma unroll
            for (int hf = 0; hf < 2; hf++) {
                float mx = -3.4e38f;
#pragma unroll
                for (int ni = 0; ni < 8; ni++)
                    mx = fmaxf(mx, fmaxf(acc[mi][ni][2*hf], acc[mi][ni][2*hf+1]));
                mx = fmaxf(mx, __shfl_xor_sync(0xffffffffu, mx, 1));
                mx = fmaxf(mx, __shfl_xor_sync(0xffffffffu, mx, 2));
                float s = 0.f;
#pragma unroll
                for (int ni = 0; ni < 8; ni++) {
                    float e0 = expf(acc[mi][ni][2*hf]     - mx);
                    float e1 = expf(acc[mi][ni][2*hf + 1] - mx);
                    acc[mi][ni][2*hf] = e0; acc[mi][ni][2*hf+1] = e1;
                    s += e0 + e1;
                }
                s += __shfl_xor_sync(0xffffffffu, s, 1);
                s += __shfl_xor_sync(0xffffffffu, s, 2);
                float inv = 1.f / s;
#pragma unroll
                for (int ni = 0; ni < 8; ni++) {
                    acc[mi][ni][2*hf]     *= inv;
                    acc[mi][ni][2*hf + 1] *= inv;
                }
            }
        }
    }

    // epilogue: route by column block (uniform per warp)
    float* Cp; int cb; int ldc;
    if (colbase < csplit) { Cp = C1; cb = colbase; ldc = ld1; }
    else                  { Cp = C2; cb = colbase - csplit; ldc = ld2; }

    const int g = lane >> 2, t = lane & 3;
#pragma unroll
    for (int mi = 0; mi < 2; mi++) {
        int r = bm + warpM * 32 + mi * 16 + g;
#pragma unroll
        for (int ni = 0; ni < 8; ni++) {
            int co = cb + ni * 8 + t * 2;
            float b0 = 0.f, b1 = 0.f;
            if (bias) { b0 = bias[co]; b1 = bias[co + 1]; }
            float2 v0 = {acc[mi][ni][0] + b0, acc[mi][ni][1] + b1};
            float2 v1 = {acc[mi][ni][2] + b0, acc[mi][ni][3] + b1};
            *(float2*)(Cp + (size_t)r * ldc + co)       = v0;
            *(float2*)(Cp + (size_t)(r + 8) * ldc + co) = v1;
        }
    }
}

// ---------------------------------------------------------------------------
// split x (fp32 -> bf16 hi/lo)
// ---------------------------------------------------------------------------
__global__ __launch_bounds__(256) void split_x_kernel(const float* __restrict__ x)
{
    int i = blockIdx.x * 256 + threadIdx.x;
    float4 v = ((const float4*)x)[i];
    float f[4] = {v.x, v.y, v.z, v.w};
    __nv_bfloat162 h01, h23, l01, l23;
    __nv_bfloat16 h, l;
    h = __float2bfloat16_rn(f[0]); l = __float2bfloat16_rn(f[0] - __bfloat162float(h)); h01.x = h; l01.x = l;
    h = __float2bfloat16_rn(f[1]); l = __float2bfloat16_rn(f[1] - __bfloat162float(h)); h01.y = h; l01.y = l;
    h = __float2bfloat16_rn(f[2]); l = __float2bfloat16_rn(f[2] - __bfloat162float(h)); h23.x = h; l23.x = l;
    h = __float2bfloat16_rn(f[3]); l = __float2bfloat16_rn(f[3] - __bfloat162float(h)); h23.y = h; l23.y = l;
    ((__nv_bfloat162*)g_xh)[2 * i] = h01; ((__nv_bfloat162*)g_xh)[2 * i + 1] = h23;
    ((__nv_bfloat162*)g_xl)[2 * i] = l01; ((__nv_bfloat162*)g_xl)[2 * i + 1] = l23;
}

// ---------------------------------------------------------------------------
// all-weights transpose + split (z selects which weight)
// ---------------------------------------------------------------------------
__global__ __launch_bounds__(256) void wsplit_all_kernel(
    const float* __restrict__ wq, const float* __restrict__ wkv,
    const float* __restrict__ wp)
{
    __shared__ float t[32][33];
    const int z = blockIdx.z;
    const float* W; __nv_bfloat16 *Th, *Tl; int K, N, roff;
    if (z == 0)      { W = wq;  K = DIMV; N = DIMV; Th = g_wqkvh; Tl = g_wqkvl; roff = 0;   }
    else if (z == 1) { W = wkv; K = DIMV; N = EDIM; Th = g_wqkvh; Tl = g_wqkvl; roff = DIMV;}
    else             { W = wp;  K = EDIM; N = DIMV; Th = g_wph;   Tl = g_wpl;   roff = 0;   }

    int n0 = blockIdx.x * 32, k0 = blockIdx.y * 32;
    if (n0 >= N || k0 >= K) return;
    int tx = threadIdx.x & 31, ty = threadIdx.x >> 5;
#pragma unroll
    for (int i = 0; i < 4; i++)
        t[ty + i * 8][tx] = W[(size_t)(k0 + ty + i * 8) * N + n0 + tx];
    __syncthreads();
#pragma unroll
    for (int i = 0; i < 4; i++) {
        float f = t[tx][ty + i * 8];
        __nv_bfloat16 h = __float2bfloat16_rn(f);
        __nv_bfloat16 l = __float2bfloat16_rn(f - __bfloat162float(h));
        Th[(size_t)(roff + n0 + ty + i * 8) * K + k0 + tx] = h;
        Tl[(size_t)(roff + n0 + ty + i * 8) * K + k0 + tx] = l;
    }
}

// ---------------------------------------------------------------------------
// ktv partials: block (bh, s); 4x4 per-thread tiles over a 128-row chunk.
// ---------------------------------------------------------------------------
__global__ __launch_bounds__(256) void ktv_part_kernel()
{
    int bh = blockIdx.x, s = blockIdx.y;
    int b = bh / HEADS, h = bh % HEADS;
    const int chunk = NN / KTV_SPLIT;            // 128
    const float* ksp = g_kv + (size_t)b * NN * EDIM + h * HD + (size_t)s * chunk * EDIM;
    const float* vp  = ksp + DIMV;

    __shared__ float Ks[32][64];
    __shared__ float Vs[32][64];

    int tid = threadIdx.x;
    int td = tid & 15, te = tid >> 4;
    float acc[4][4];
#pragma unroll
    for (int i = 0; i < 4; i++)
#pragma unroll
        for (int j = 0; j < 4; j++) acc[i][j] = 0.f;

    for (int n0 = 0; n0 < chunk; n0 += 32) {
#pragma unroll
        for (int i = 0; i < 2; i++) {
            int idx4 = tid + i * 256;
            int nl = idx4 >> 4, d4 = (idx4 & 15) * 4;
            *(float4*)&Ks[nl][d4] = *(const float4*)(ksp + (size_t)(n0 + nl) * EDIM + d4);
            *(float4*)&Vs[nl][d4] = *(const float4*)(vp  + (size_t)(n0 + nl) * EDIM + d4);
        }
        __syncthreads();
#pragma unroll 8
        for (int n = 0; n < 32; n++) {
            float a0[4], b0[4];
            *(float4*)a0 = *(const float4*)&Ks[n][td * 4];
            *(float4*)b0 = *(const float4*)&Vs[n][te * 4];
#pragma unroll
            for (int i = 0; i < 4; i++)
#pragma unroll
                for (int j = 0; j < 4; j++)
                    acc[i][j] += a0[i] * b0[j];
        }
        __syncthreads();
    }

    float* out = g_ktvp + ((size_t)s * 96 + bh) * HD * HD;
#pragma unroll
    for (int i = 0; i < 4; i++) {
        float4 v;
        v.x = acc[i][0]; v.y = acc[i][1]; v.z = acc[i][2]; v.w = acc[i][3];
        *(float4*)&out[(td * 4 + i) * HD + te * 4] = v;
    }
}

// reduce partials and scatter into both ektv positions (direct + rolled)
__global__ void ktv_reduce_kernel()
{
    int idx = blockIdx.x * 256 + threadIdx.x;
    float s = 0.f;
#pragma unroll
    for (int i = 0; i < KTV_SPLIT; i++)
        s += g_ktvp[(size_t)i * 96 * HD * HD + idx];

    int e = idx & 63;
    int d = (idx >> 6) & 63;
    int bh = idx >> 12;
    int h = bh % HEADS, b = bh / HEADS;
    g_ektv[(((size_t)(b * 24 + h) * 64) + d) * 64 + e] = s;
    int ct = h * 64 + e - 32;
    if (ct < 0) ct += 768;
    int j2 = 12 + (ct >> 6), e2 = ct & 63;
    g_ektv[(((size_t)(b * 24 + j2) * 64) + d) * 64 + e2] = s;
}

// ---------------------------------------------------------------------------
// Fused attn + LePE, rolling 3-slab ring over YG consecutive image rows.
// ---------------------------------------------------------------------------
#define YG 8
#define QS_STRIDE 72
#define AL_ES   0
#define AL_QS   16384
#define AL_WT   (AL_QS + 3*64*QS_STRIDE*4)
#define AL_BS   (AL_WT + 64*9*4)
#define AL_SMEM (AL_BS + 256)

__global__ __launch_bounds__(256) void attn_lepe_kernel(
    const float* __restrict__ w_lepe, const float* __restrict__ b_lepe)
{
    extern __shared__ char sm[];
    float* Es = (float*)(sm + AL_ES);        // [64][64]
    float* Qs = (float*)(sm + AL_QS);        // [3][64][QS_STRIDE] ring
    float* Wt = (float*)(sm + AL_WT);        // [64][9]
    float* Bs = (float*)(sm + AL_BS);        // [64]

    const int Y = blockIdx.x * YG, j = blockIdx.y, b = blockIdx.z;
    const int tid = threadIdx.x;

    const float* ep = g_ektv + (size_t)((b * 24 + j) * 64) * 64;
#pragma unroll
    for (int i = 0; i < 4; i++) {
        int idx4 = tid + i * 256;
        *(float4*)&Es[idx4 * 4] = *(const float4*)(ep + idx4 * 4);
    }
    for (int idx = tid; idx < 64 * 9; idx += 256) Wt[idx] = w_lepe[(j * 64) * 9 + idx];
    if (tid < 64) Bs[tid] = b_lepe[j * 64 + tid];

    const int qbase = (j < 12) ? j * 64 : ((j - 12) * 64 + 32);

    auto load_slab = [&](int y) {
        float* dst = Qs + ((y + 1) % 3) * 64 * QS_STRIDE;
        bool valid = (y >= 0) && (y < 64);
        const float* qrow = g_q + ((size_t)(b * NN) + y * 64) * DIMV;
#pragma unroll
        for (int i = 0; i < 4; i++) {
            int idx4 = tid + i * 256;
            int x = idx4 >> 4, d4 = (idx4 & 15) * 4;
            float4 v = make_float4(0.f, 0.f, 0.f, 0.f);
            if (valid) {
                int c = qbase + d4;
                if (c >= 768) c -= 768;
                v = *(const float4*)(qrow + (size_t)x * DIMV + c);
            }
            *(float4*)&dst[x * QS_STRIDE + d4] = v;
        }
    };

    load_slab(Y - 1);
    load_slab(Y);

    const int r0 = (tid >> 4) * 4, e0 = (tid & 15) * 4;

    for (int yi = 0; yi < YG; yi++) {
        const int y0 = Y + yi;
        load_slab(y0 + 1);
        __syncthreads();

        const float* Qc = Qs + ((y0 + 1) % 3) * 64 * QS_STRIDE;
        float acc[4][4];
#pragma unroll
        for (int i = 0; i < 4; i++)
#pragma unroll
            for (int jj = 0; jj < 4; jj++) acc[i][jj] = 0.f;

#pragma unroll 8
        for (int d = 0; d < 64; d++) {
            float a0[4], b0[4];
            a0[0] = Qc[(r0 + 0) * QS_STRIDE + d];
            a0[1] = Qc[(r0 + 1) * QS_STRIDE + d];
            a0[2] = Qc[(r0 + 2) * QS_STRIDE + d];
            a0[3] = Qc[(r0 + 3) * QS_STRIDE + d];
            *(float4*)b0 = *(const float4*)&Es[d * 64 + e0];
#pragma unroll
            for (int i = 0; i < 4; i++)
#pragma unroll
                for (int jj = 0; jj < 4; jj++)
                    acc[i][jj] += a0[i] * b0[jj];
        }

        const float* slab0 = Qs + ((y0 + 0) % 3) * 64 * QS_STRIDE;
        const float* slab1 = Qc;
        const float* slab2 = Qs + ((y0 + 2) % 3) * 64 * QS_STRIDE;
        const float* slabs[3] = {slab0, slab1, slab2};

        const int n0 = y0 * 64;
#pragma unroll
        for (int i = 0; i < 4; i++) {
            const int x = r0 + i;
            uint32_t hp[2], lp[2];
#pragma unroll
            for (int jj = 0; jj < 4; jj++) {
                const int e = e0 + jj;
                float sum = Bs[e];
#pragma unroll
                for (int ky = 0; ky < 3; ky++) {
#pragma unroll
                    for (int kx = 0; kx < 3; kx++) {
                        int xx = x + kx - 1;
                        float qv = (xx >= 0 && xx < 64) ? slabs[ky][xx * QS_STRIDE + e] : 0.f;
                        sum += Wt[e * 9 + ky * 3 + kx] * qv;
                    }
                }
                float val = 0.125f * acc[i][jj] + sum;
                __nv_bfloat16 h = __float2bfloat16_rn(val);
                __nv_bfloat16 l = __float2bfloat16_rn(val - __bfloat162float(h));
                ((__nv_bfloat16*)hp)[jj] = h;
                ((__nv_bfloat16*)lp)[jj] = l;
            }
            size_t off = ((size_t)(b * NN) + n0 + x) * EDIM + j * 64 + e0;
            *(uint2*)(g_yh + off) = make_uint2(hp[0], hp[1]);
            *(uint2*)(g_yl + off) = make_uint2(lp[0], lp[1]);
        }
        __syncthreads();
    }
}

// ---------------------------------------------------------------------------
extern "C" void kernel_launch(void* const* d_in, const int* in_sizes, int n_in,
                              void* d_out, int out_size)
{
    const float* x      = (const float*)d_in[0];
    const float* w_q    = (const float*)d_in[1];
    const float* w_kv   = (const float*)d_in[2];
    const float* w_proj = (const float*)d_in[3];
    const float* b_proj = (const float*)d_in[4];
    const float* w_lepe = (const float*)d_in[5];
    const float* b_lepe = (const float*)d_in[6];
    float* out = (float*)d_out;

    float* q = nullptr; float* kv = nullptr;
    cudaGetSymbolAddress((void**)&q,  g_q);
    cudaGetSymbolAddress((void**)&kv, g_kv);
    __nv_bfloat16 *xh, *xl, *yh, *yl, *wh, *wl, *wph, *wpl;
    cudaGetSymbolAddress((void**)&xh, g_xh);   cudaGetSymbolAddress((void**)&xl, g_xl);
    cudaGetSymbolAddress((void**)&yh, g_yh);   cudaGetSymbolAddress((void**)&yl, g_yl);
    cudaGetSymbolAddress((void**)&wh, g_wqkvh); cudaGetSymbolAddress((void**)&wl, g_wqkvl);
    cudaGetSymbolAddress((void**)&wph, g_wph); cudaGetSymbolAddress((void**)&wpl, g_wpl);

    static bool attr_set = false;
    if (!attr_set) {
        cudaFuncSetAttribute(gemm_mma, cudaFuncAttributeMaxDynamicSharedMemorySize, GEMM_DSMEM);
        cudaFuncSetAttribute(attn_lepe_kernel, cudaFuncAttributeMaxDynamicSharedMemorySize, AL_SMEM);
        attr_set = true;
    }

    // 0-1: operand splits
    split_x_kernel<<<(MTOT * DIMV / 4) / 256, 256>>>(x);
    wsplit_all_kernel<<<dim3(48, 48, 3), 256>>>(w_q, w_kv, w_proj);

    // 2: merged q|kv projection with fused k-softmax on cols [768,1536)
    gemm_mma<<<dim3(NQKV / 128, MTOT / 128), 256, GEMM_DSMEM>>>(
        xh, xl, wh, wl, q, kv, DIMV, DIMV, EDIM,
        MTOT, NQKV, DIMV, nullptr, DIMV, 2 * DIMV);

    // 3-4: K^T V split + reduce (scatters into ektv)
    ktv_part_kernel<<<dim3(BB * HEADS, KTV_SPLIT), 256>>>();
    ktv_reduce_kernel<<<(BB * HEADS * HD * HD) / 256, 256>>>();

    // 5: fused attn + LePE (rolling slabs) -> yh/yl
    attn_lepe_kernel<<<dim3(64 / YG, 24, BB), 256, AL_SMEM>>>(w_lepe, b_lepe);

    // 6: output projection + bias
    gemm_mma<<<dim3(DIMV / 128, MTOT / 128), 256, GEMM_DSMEM>>>(
        yh, yl, wph, wpl, out, out, DIMV, DIMV, DIMV,
        MTOT, DIMV, EDIM, b_proj, 0, 0);
}

// round 17
// speedup vs baseline: 1.0122x; 1.0122x over previous
#include <cuda_runtime.h>
#include <cuda_bf16.h>
#include <cstdint>

// Problem constants
#define BB    8
#define NN    4096
#define DIMV  768
#define HEADS 12
#define HD    64
#define EDIM  1536
#define MTOT  (BB*NN)   // 32768
#define KTV_SPLIT 32
#define NQKV  2304      // merged q|kv output width

// Scratch (static device allocations)
__device__ float g_q   [(size_t)MTOT * DIMV];
__device__ float g_kv  [(size_t)MTOT * EDIM];   // k cols 0..767 softmaxed (fused)
__device__ float g_ktvp[(size_t)KTV_SPLIT * BB * HEADS * HD * HD];
__device__ float g_ektv[BB * 2*HEADS * HD * HD];

// bf16 hi/lo split operands
__device__ __nv_bfloat16 g_xh[(size_t)MTOT * DIMV];
__device__ __nv_bfloat16 g_xl[(size_t)MTOT * DIMV];
__device__ __nv_bfloat16 g_yh[(size_t)MTOT * EDIM];
__device__ __nv_bfloat16 g_yl[(size_t)MTOT * EDIM];
// weights transposed to [N][K] + split; q|kv merged
__device__ __nv_bfloat16 g_wqkvh[NQKV * DIMV];
__device__ __nv_bfloat16 g_wqkvl[NQKV * DIMV];
__device__ __nv_bfloat16 g_wph  [DIMV * EDIM];
__device__ __nv_bfloat16 g_wpl  [DIMV * EDIM];

// ---------------------------------------------------------------------------
// MMA / cp.async / f32x2 helpers
// ---------------------------------------------------------------------------
__device__ __forceinline__ void ldsm_x4p(uint32_t r[4], const void* p) {
    uint32_t a = (uint32_t)__cvta_generic_to_shared(p);
    asm volatile("ldmatrix.sync.aligned.m8n8.x4.shared.b16 {%0,%1,%2,%3}, [%4];"
                 : "=r"(r[0]), "=r"(r[1]), "=r"(r[2]), "=r"(r[3]) : "r"(a));
}
__device__ __forceinline__ void mma16816(float c[4], const uint32_t a[4],
                                         uint32_t b0, uint32_t b1) {
    asm volatile(
        "mma.sync.aligned.m16n8k16.row.col.f32.bf16.bf16.f32 "
        "{%0,%1,%2,%3}, {%4,%5,%6,%7}, {%8,%9}, {%0,%1,%2,%3};"
        : "+f"(c[0]), "+f"(c[1]), "+f"(c[2]), "+f"(c[3])
        : "r"(a[0]), "r"(a[1]), "r"(a[2]), "r"(a[3]), "r"(b0), "r"(b1));
}
__device__ __forceinline__ void cp_async16(void* smem_dst, const void* gsrc) {
    uint32_t a = (uint32_t)__cvta_generic_to_shared(smem_dst);
    asm volatile("cp.async.cg.shared.global [%0], [%1], 16;" :: "r"(a), "l"(gsrc));
}
#define CP_COMMIT() asm volatile("cp.async.commit_group;" ::: "memory")
#define CP_WAIT0()  asm volatile("cp.async.wait_group 0;" ::: "memory")
#define CP_WAIT1()  asm volatile("cp.async.wait_group 1;" ::: "memory")

// packed fp32x2 FMA (per-lane IEEE fp32; bit-identical to scalar fmaf order)
__device__ __forceinline__ unsigned long long pack_dup(float a) {
    unsigned long long r;
    asm("mov.b64 %0, {%1, %1};" : "=l"(r) : "r"(__float_as_uint(a)));
    return r;
}
__device__ __forceinline__ void ffma2(unsigned long long& d, unsigned long long a,
                                      unsigned long long b) {
    asm("fma.rn.f32x2 %0, %1, %2, %0;" : "+l"(d) : "l"(a), "l"(b));
}
__device__ __forceinline__ void unpack2(unsigned long long v, float& lo, float& hi) {
    uint32_t l, h;
    asm("mov.b64 {%0, %1}, %2;" : "=r"(l), "=r"(h) : "l"(v));
    lo = __uint_as_float(l); hi = __uint_as_float(h);
}

// SW128 swizzle on (row, 16B-chunk) within a 128x32 bf16 tile (64 B rows)
__device__ __forceinline__ int sw_off(int row, int chunk) {
    int byte = row * 64 + chunk * 16;
    return byte ^ ((byte >> 3) & 0x70);
}

#define TILE_SW  8192
#define STAGE_SW (4 * TILE_SW)
#define NSTAGE   3
#define GEMM_DSMEM (NSTAGE * STAGE_SW)  // 98304 B

// ---------------------------------------------------------------------------
// bf16x3 tensor-core GEMM, 3-stage cp.async pipeline, 128x128, 2 CTAs/SM.
// (round-15 inner loop — B-frag double buffering reverted, measured neutral)
// ---------------------------------------------------------------------------
__global__ __launch_bounds__(256, 2) void gemm_mma(
    const __nv_bfloat16* __restrict__ Ah, const __nv_bfloat16* __restrict__ Al,
    const __nv_bfloat16* __restrict__ Bh, const __nv_bfloat16* __restrict__ Bl,
    float* __restrict__ C1, float* __restrict__ C2, int csplit, int ld1, int ld2,
    int M, int N, int K, const float* __restrict__ bias, int sm_lo, int sm_hi)
{
    extern __shared__ char smem[];

    const int tid  = threadIdx.x;
    const int lane = tid & 31;
    const int warp = tid >> 5;
    const int warpM = warp >> 1;
    const int warpN = warp & 1;
    const int bm = blockIdx.y * 128;
    const int bn = blockIdx.x * 128;

    float acc[2][8][4];
#pragma unroll
    for (int i = 0; i < 2; i++)
#pragma unroll
        for (int j = 0; j < 8; j++)
#pragma unroll
            for (int l = 0; l < 4; l++) acc[i][j][l] = 0.f;

    const int aRow = warpM * 32 + (lane & 7) + ((lane & 8) ? 8 : 0);
    const int bRow = warpN * 64 + (lane & 7) + ((lane & 16) ? 8 : 0);

    int offA[2][2], offB[4][2];
#pragma unroll
    for (int mi = 0; mi < 2; mi++)
#pragma unroll
        for (int ks = 0; ks < 2; ks++)
            offA[mi][ks] = sw_off(aRow + mi * 16, ks * 2 + ((lane & 16) ? 1 : 0));
#pragma unroll
    for (int n2 = 0; n2 < 4; n2++)
#pragma unroll
        for (int ks = 0; ks < 2; ks++)
            offB[n2][ks] = sw_off(bRow + n2 * 16, ks * 2 + ((lane & 8) ? 1 : 0));

    const __nv_bfloat16* srcs[4] = {Ah, Al, Bh, Bl};
    const int rowbase[4] = {bm, bm, bn, bn};
    const int row = tid >> 1;
    const int ch0 = (tid & 1) * 2;
    int stg_off[2];
    stg_off[0] = sw_off(row, ch0);
    stg_off[1] = sw_off(row, ch0 + 1);

    auto issue_stage = [&](int kt, int sidx) {
        char* st = smem + sidx * STAGE_SW;
        const int k0 = kt << 5;
#pragma unroll
        for (int p = 0; p < 4; p++) {
            const __nv_bfloat16* src = srcs[p] + (size_t)(rowbase[p] + row) * K + k0;
#pragma unroll
            for (int c = 0; c < 2; c++)
                cp_async16(st + p * TILE_SW + stg_off[c], src + (ch0 + c) * 8);
        }
    };

    const int NK = K >> 5;
    issue_stage(0, 0);
    CP_COMMIT();
    issue_stage(1, 1);
    CP_COMMIT();

    int s3 = 0;
    for (int kt = 0; kt < NK; kt++) {
        if (kt == NK - 1) { CP_WAIT0(); } else { CP_WAIT1(); }
        __syncthreads();
        if (kt + 2 < NK) {
            int si = s3 + 2; if (si >= 3) si -= 3;
            issue_stage(kt + 2, si);
            CP_COMMIT();
        }

        const char* st = smem + s3 * STAGE_SW;
#pragma unroll
        for (int ks = 0; ks < 2; ks++) {
            uint32_t ah[2][4], al[2][4];
#pragma unroll
            for (int mi = 0; mi < 2; mi++) {
                ldsm_x4p(ah[mi], st + offA[mi][ks]);
                ldsm_x4p(al[mi], st + TILE_SW + offA[mi][ks]);
            }
#pragma unroll
            for (int n2 = 0; n2 < 4; n2++) {
                uint32_t bh[4], bl[4];
                ldsm_x4p(bh, st + 2 * TILE_SW + offB[n2][ks]);
                ldsm_x4p(bl, st + 3 * TILE_SW + offB[n2][ks]);
#pragma unroll
                for (int mi = 0; mi < 2; mi++) {
                    mma16816(acc[mi][2*n2],   ah[mi], bh[0], bh[1]);
                    mma16816(acc[mi][2*n2+1], ah[mi], bh[2], bh[3]);
                    mma16816(acc[mi][2*n2],   ah[mi], bl[0], bl[1]);
                    mma16816(acc[mi][2*n2+1], ah[mi], bl[2], bl[3]);
                    mma16816(acc[mi][2*n2],   al[mi], bh[0], bh[1]);
                    mma16816(acc[mi][2*n2+1], al[mi], bh[2], bh[3]);
                }
            }
        }
        if (++s3 == 3) s3 = 0;
    }

    const int colbase = bn + warpN * 64;

    if (colbase >= sm_lo && colbase < sm_hi) {
#pragma unroll
        for (int mi = 0; mi < 2; mi++) {
#pragma unroll
            for (int hf = 0; hf < 2; hf++) {
                float mx = -3.4e38f;
#pragma unroll
                for (int ni = 0; ni < 8; ni++)
                    mx = fmaxf(mx, fmaxf(acc[mi][ni][2*hf], acc[mi][ni][2*hf+1]));
                mx = fmaxf(mx, __shfl_xor_sync(0xffffffffu, mx, 1));
                mx = fmaxf(mx, __shfl_xor_sync(0xffffffffu, mx, 2));
                float s = 0.f;
#pragma unroll
                for (int ni = 0; ni < 8; ni++) {
                    float e0 = expf(acc[mi][ni][2*hf]     - mx);
                    float e1 = expf(acc[mi][ni][2*hf + 1] - mx);
                    acc[mi][ni][2*hf] = e0; acc[mi][ni][2*hf+1] = e1;
                    s += e0 + e1;
                }
                s += __shfl_xor_sync(0xffffffffu, s, 1);
                s += __shfl_xor_sync(0xffffffffu, s, 2);
                float inv = 1.f / s;
#pragma unroll
                for (int ni = 0; ni < 8; ni++) {
                    acc[mi][ni][2*hf]     *= inv;
                    acc[mi][ni][2*hf + 1] *= inv;
                }
            }
        }
    }

    float* Cp; int cb; int ldc;
    if (colbase < csplit) { Cp = C1; cb = colbase; ldc = ld1; }
    else                  { Cp = C2; cb = colbase - csplit; ldc = ld2; }

    const int g = lane >> 2, t = lane & 3;
#pragma unroll
    for (int mi = 0; mi < 2; mi++) {
        int r = bm + warpM * 32 + mi * 16 + g;
#pragma unroll
        for (int ni = 0; ni < 8; ni++) {
            int co = cb + ni * 8 + t * 2;
            float b0 = 0.f, b1 = 0.f;
            if (bias) { b0 = bias[co]; b1 = bias[co + 1]; }
            float2 v0 = {acc[mi][ni][0] + b0, acc[mi][ni][1] + b1};
            float2 v1 = {acc[mi][ni][2] + b0, acc[mi][ni][3] + b1};
            *(float2*)(Cp + (size_t)r * ldc + co)       = v0;
            *(float2*)(Cp + (size_t)(r + 8) * ldc + co) = v1;
        }
    }
}

// ---------------------------------------------------------------------------
// split x (fp32 -> bf16 hi/lo)
// ---------------------------------------------------------------------------
__global__ __launch_bounds__(256) void split_x_kernel(const float* __restrict__ x)
{
    int i = blockIdx.x * 256 + threadIdx.x;
    float4 v = ((const float4*)x)[i];
    float f[4] = {v.x, v.y, v.z, v.w};
    __nv_bfloat162 h01, h23, l01, l23;
    __nv_bfloat16 h, l;
    h = __float2bfloat16_rn(f[0]); l = __float2bfloat16_rn(f[0] - __bfloat162float(h)); h01.x = h; l01.x = l;
    h = __float2bfloat16_rn(f[1]); l = __float2bfloat16_rn(f[1] - __bfloat162float(h)); h01.y = h; l01.y = l;
    h = __float2bfloat16_rn(f[2]); l = __float2bfloat16_rn(f[2] - __bfloat162float(h)); h23.x = h; l23.x = l;
    h = __float2bfloat16_rn(f[3]); l = __float2bfloat16_rn(f[3] - __bfloat162float(h)); h23.y = h; l23.y = l;
    ((__nv_bfloat162*)g_xh)[2 * i] = h01; ((__nv_bfloat162*)g_xh)[2 * i + 1] = h23;
    ((__nv_bfloat162*)g_xl)[2 * i] = l01; ((__nv_bfloat162*)g_xl)[2 * i + 1] = l23;
}

// ---------------------------------------------------------------------------
// all-weights transpose + split (z selects which weight)
// ---------------------------------------------------------------------------
__global__ __launch_bounds__(256) void wsplit_all_kernel(
    const float* __restrict__ wq, const float* __restrict__ wkv,
    const float* __restrict__ wp)
{
    __shared__ float t[32][33];
    const int z = blockIdx.z;
    const float* W; __nv_bfloat16 *Th, *Tl; int K, N, roff;
    if (z == 0)      { W = wq;  K = DIMV; N = DIMV; Th = g_wqkvh; Tl = g_wqkvl; roff = 0;   }
    else if (z == 1) { W = wkv; K = DIMV; N = EDIM; Th = g_wqkvh; Tl = g_wqkvl; roff = DIMV;}
    else             { W = wp;  K = EDIM; N = DIMV; Th = g_wph;   Tl = g_wpl;   roff = 0;   }

    int n0 = blockIdx.x * 32, k0 = blockIdx.y * 32;
    if (n0 >= N || k0 >= K) return;
    int tx = threadIdx.x & 31, ty = threadIdx.x >> 5;
#pragma unroll
    for (int i = 0; i < 4; i++)
        t[ty + i * 8][tx] = W[(size_t)(k0 + ty + i * 8) * N + n0 + tx];
    __syncthreads();
#pragma unroll
    for (int i = 0; i < 4; i++) {
        float f = t[tx][ty + i * 8];
        __nv_bfloat16 h = __float2bfloat16_rn(f);
        __nv_bfloat16 l = __float2bfloat16_rn(f - __bfloat162float(h));
        Th[(size_t)(roff + n0 + ty + i * 8) * K + k0 + tx] = h;
        Tl[(size_t)(roff + n0 + ty + i * 8) * K + k0 + tx] = l;
    }
}

// ---------------------------------------------------------------------------
// ktv partials: 4x4 per-thread tiles, acc packed into f32x2 (bit-exact order)
// ---------------------------------------------------------------------------
__global__ __launch_bounds__(256) void ktv_part_kernel()
{
    int bh = blockIdx.x, s = blockIdx.y;
    int b = bh / HEADS, h = bh % HEADS;
    const int chunk = NN / KTV_SPLIT;            // 128
    const float* ksp = g_kv + (size_t)b * NN * EDIM + h * HD + (size_t)s * chunk * EDIM;
    const float* vp  = ksp + DIMV;

    __shared__ float Ks[32][64];
    __shared__ float Vs[32][64];

    int tid = threadIdx.x;
    int td = tid & 15, te = tid >> 4;
    unsigned long long accp[4][2];
#pragma unroll
    for (int i = 0; i < 4; i++) { accp[i][0] = 0ULL; accp[i][1] = 0ULL; }

    for (int n0 = 0; n0 < chunk; n0 += 32) {
#pragma unroll
        for (int i = 0; i < 2; i++) {
            int idx4 = tid + i * 256;
            int nl = idx4 >> 4, d4 = (idx4 & 15) * 4;
            *(float4*)&Ks[nl][d4] = *(const float4*)(ksp + (size_t)(n0 + nl) * EDIM + d4);
            *(float4*)&Vs[nl][d4] = *(const float4*)(vp  + (size_t)(n0 + nl) * EDIM + d4);
        }
        __syncthreads();
#pragma unroll 8
        for (int n = 0; n < 32; n++) {
            float a0[4];
            *(float4*)a0 = *(const float4*)&Ks[n][td * 4];
            unsigned long long b01 = __double_as_longlong(*(const double*)&Vs[n][te * 4]);
            unsigned long long b23 = __double_as_longlong(*(const double*)&Vs[n][te * 4 + 2]);
#pragma unroll
            for (int i = 0; i < 4; i++) {
                unsigned long long ap = pack_dup(a0[i]);
                ffma2(accp[i][0], ap, b01);
                ffma2(accp[i][1], ap, b23);
            }
        }
        __syncthreads();
    }

    float* out = g_ktvp + ((size_t)s * 96 + bh) * HD * HD;
#pragma unroll
    for (int i = 0; i < 4; i++) {
        float4 v;
        unpack2(accp[i][0], v.x, v.y);
        unpack2(accp[i][1], v.z, v.w);
        *(float4*)&out[(td * 4 + i) * HD + te * 4] = v;
    }
}

// reduce partials and scatter into both ektv positions (direct + rolled)
__global__ void ktv_reduce_kernel()
{
    int idx = blockIdx.x * 256 + threadIdx.x;
    float s = 0.f;
#pragma unroll
    for (int i = 0; i < KTV_SPLIT; i++)
        s += g_ktvp[(size_t)i * 96 * HD * HD + idx];

    int e = idx & 63;
    int d = (idx >> 6) & 63;
    int bh = idx >> 12;
    int h = bh % HEADS, b = bh / HEADS;
    g_ektv[(((size_t)(b * 24 + h) * 64) + d) * 64 + e] = s;
    int ct = h * 64 + e - 32;
    if (ct < 0) ct += 768;
    int j2 = 12 + (ct >> 6), e2 = ct & 63;
    g_ektv[(((size_t)(b * 24 + j2) * 64) + d) * 64 + e2] = s;
}

// ---------------------------------------------------------------------------
// Fused attn + LePE, rolling 3-slab ring; attn inner loop on packed f32x2.
// ---------------------------------------------------------------------------
#define YG 8
#define QS_STRIDE 72
#define AL_ES   0
#define AL_QS   16384
#define AL_WT   (AL_QS + 3*64*QS_STRIDE*4)
#define AL_BS   (AL_WT + 64*9*4)
#define AL_SMEM (AL_BS + 256)

__global__ __launch_bounds__(256) void attn_lepe_kernel(
    const float* __restrict__ w_lepe, const float* __restrict__ b_lepe)
{
    extern __shared__ char sm[];
    float* Es = (float*)(sm + AL_ES);        // [64][64]
    float* Qs = (float*)(sm + AL_QS);        // [3][64][QS_STRIDE] ring
    float* Wt = (float*)(sm + AL_WT);        // [64][9]
    float* Bs = (float*)(sm + AL_BS);        // [64]

    const int Y = blockIdx.x * YG, j = blockIdx.y, b = blockIdx.z;
    const int tid = threadIdx.x;

    const float* ep = g_ektv + (size_t)((b * 24 + j) * 64) * 64;
#pragma unroll
    for (int i = 0; i < 4; i++) {
        int idx4 = tid + i * 256;
        *(float4*)&Es[idx4 * 4] = *(const float4*)(ep + idx4 * 4);
    }
    for (int idx = tid; idx < 64 * 9; idx += 256) Wt[idx] = w_lepe[(j * 64) * 9 + idx];
    if (tid < 64) Bs[tid] = b_lepe[j * 64 + tid];

    const int qbase = (j < 12) ? j * 64 : ((j - 12) * 64 + 32);

    auto load_slab = [&](int y) {
        float* dst = Qs + ((y + 1) % 3) * 64 * QS_STRIDE;
        bool valid = (y >= 0) && (y < 64);
        const float* qrow = g_q + ((size_t)(b * NN) + y * 64) * DIMV;
#pragma unroll
        for (int i = 0; i < 4; i++) {
            int idx4 = tid + i * 256;
            int x = idx4 >> 4, d4 = (idx4 & 15) * 4;
            float4 v = make_float4(0.f, 0.f, 0.f, 0.f);
            if (valid) {
                int c = qbase + d4;
                if (c >= 768) c -= 768;
                v = *(const float4*)(qrow + (size_t)x * DIMV + c);
            }
            *(float4*)&dst[x * QS_STRIDE + d4] = v;
        }
    };

    load_slab(Y - 1);
    load_slab(Y);

    const int r0 = (tid >> 4) * 4, e0 = (tid & 15) * 4;

    for (int yi = 0; yi < YG; yi++) {
        const int y0 = Y + yi;
        load_slab(y0 + 1);
        __syncthreads();

        const float* Qc = Qs + ((y0 + 1) % 3) * 64 * QS_STRIDE;
        unsigned long long accp[4][2];
#pragma unroll
        for (int i = 0; i < 4; i++) { accp[i][0] = 0ULL; accp[i][1] = 0ULL; }

#pragma unroll 8
        for (int d = 0; d < 64; d++) {
            float a0[4];
            a0[0] = Qc[(r0 + 0) * QS_STRIDE + d];
            a0[1] = Qc[(r0 + 1) * QS_STRIDE + d];
            a0[2] = Qc[(r0 + 2) * QS_STRIDE + d];
            a0[3] = Qc[(r0 + 3) * QS_STRIDE + d];
            unsigned long long b01 = __double_as_longlong(*(const double*)&Es[d * 64 + e0]);
            unsigned long long b23 = __double_as_longlong(*(const double*)&Es[d * 64 + e0 + 2]);
#pragma unroll
            for (int i = 0; i < 4; i++) {
                unsigned long long ap = pack_dup(a0[i]);
                ffma2(accp[i][0], ap, b01);
                ffma2(accp[i][1], ap, b23);
            }
        }

        float acc[4][4];
#pragma unroll
        for (int i = 0; i < 4; i++) {
            unpack2(accp[i][0], acc[i][0], acc[i][1]);
            unpack2(accp[i][1], acc[i][2], acc[i][3]);
        }

        const float* slab0 = Qs + ((y0 + 0) % 3) * 64 * QS_STRIDE;
        const float* slab1 = Qc;
        const float* slab2 = Qs + ((y0 + 2) % 3) * 64 * QS_STRIDE;
        const float* slabs[3] = {slab0, slab1, slab2};

        const int n0 = y0 * 64;
#pragma unroll
        for (int i = 0; i < 4; i++) {
            const int x = r0 + i;
            uint32_t hp[2], lp[2];
#pragma unroll
            for (int jj = 0; jj < 4; jj++) {
                const int e = e0 + jj;
                float sum = Bs[e];
#pragma unroll
                for (int ky = 0; ky < 3; ky++) {
#pragma unroll
                    for (int kx = 0; kx < 3; kx++) {
                        int xx = x + kx - 1;
                        float qv = (xx >= 0 && xx < 64) ? slabs[ky][xx * QS_STRIDE + e] : 0.f;
                        sum += Wt[e * 9 + ky * 3 + kx] * qv;
                    }
                }
                float val = 0.125f * acc[i][jj] + sum;
                __nv_bfloat16 h = __float2bfloat16_rn(val);
                __nv_bfloat16 l = __float2bfloat16_rn(val - __bfloat162float(h));
                ((__nv_bfloat16*)hp)[jj] = h;
                ((__nv_bfloat16*)lp)[jj] = l;
            }
            size_t off = ((size_t)(b * NN) + n0 + x) * EDIM + j * 64 + e0;
            *(uint2*)(g_yh + off) = make_uint2(hp[0], hp[1]);
            *(uint2*)(g_yl + off) = make_uint2(lp[0], lp[1]);
        }
        __syncthreads();
    }
}

// ---------------------------------------------------------------------------
extern "C" void kernel_launch(void* const* d_in, const int* in_sizes, int n_in,
                              void* d_out, int out_size)
{
    const float* x      = (const float*)d_in[0];
    const float* w_q    = (const float*)d_in[1];
    const float* w_kv   = (const float*)d_in[2];
    const float* w_proj = (const float*)d_in[3];
    const float* b_proj = (const float*)d_in[4];
    const float* w_lepe = (const float*)d_in[5];
    const float* b_lepe = (const float*)d_in[6];
    float* out = (float*)d_out;

    float* q = nullptr; float* kv = nullptr;
    cudaGetSymbolAddress((void**)&q,  g_q);
    cudaGetSymbolAddress((void**)&kv, g_kv);
    __nv_bfloat16 *xh, *xl, *yh, *yl, *wh, *wl, *wph, *wpl;
    cudaGetSymbolAddress((void**)&xh, g_xh);   cudaGetSymbolAddress((void**)&xl, g_xl);
    cudaGetSymbolAddress((void**)&yh, g_yh);   cudaGetSymbolAddress((void**)&yl, g_yl);
    cudaGetSymbolAddress((void**)&wh, g_wqkvh); cudaGetSymbolAddress((void**)&wl, g_wqkvl);
    cudaGetSymbolAddress((void**)&wph, g_wph); cudaGetSymbolAddress((void**)&wpl, g_wpl);

    static bool attr_set = false;
    if (!attr_set) {
        cudaFuncSetAttribute(gemm_mma, cudaFuncAttributeMaxDynamicSharedMemorySize, GEMM_DSMEM);
        cudaFuncSetAttribute(attn_lepe_kernel, cudaFuncAttributeMaxDynamicSharedMemorySize, AL_SMEM);
        attr_set = true;
    }

    // 0-1: operand splits
    split_x_kernel<<<(MTOT * DIMV / 4) / 256, 256>>>(x);
    wsplit_all_kernel<<<dim3(48, 48, 3), 256>>>(w_q, w_kv, w_proj);

    // 2: merged q|kv projection with fused k-softmax on cols [768,1536)
    gemm_mma<<<dim3(NQKV / 128, MTOT / 128), 256, GEMM_DSMEM>>>(
        xh, xl, wh, wl, q, kv, DIMV, DIMV, EDIM,
        MTOT, NQKV, DIMV, nullptr, DIMV, 2 * DIMV);

    // 3-4: K^T V split + reduce (scatters into ektv)
    ktv_part_kernel<<<dim3(BB * HEADS, KTV_SPLIT), 256>>>();
    ktv_reduce_kernel<<<(BB * HEADS * HD * HD) / 256, 256>>>();

    // 5: fused attn + LePE (rolling slabs) -> yh/yl
    attn_lepe_kernel<<<dim3(64 / YG, 24, BB), 256, AL_SMEM>>>(w_lepe, b_lepe);

    // 6: output projection + bias
    gemm_mma<<<dim3(DIMV / 128, MTOT / 128), 256, GEMM_DSMEM>>>(
        yh, yl, wph, wpl, out, out, DIMV, DIMV, DIMV,
        MTOT, DIMV, EDIM, b_proj, 0, 0);
}